// round 1
// baseline (speedup 1.0000x reference)
#include <cuda_runtime.h>

// NeighborhoodAttention 3D, exact-window (no halo waste), fp32 SIMT flash.
// Shapes fixed by the problem: B=1, T=16, H=32, W=32, nh=8, D=128, window (3,7,7).
#define Tz 16
#define Hz 32
#define Wz 32
#define NH 8
#define DD 128
#define KT 3
#define KH 7
#define KW 7
#define NKEYS (KT * KH * KW)   // 147

// CTA = 128 threads = 4 warps; handles a (1 x 2 x 8) query group for one head.
// Each warp processes 4 consecutive-w queries serially (windows overlap 6/7 ->
// high L1 temporal reuse of K/V lines). Per query:
//   pass1: 147 scores via lane-parallel dot (lane owns 4 dims) + butterfly reduce
//   pass2: softmax (scores staged in smem)
//   pass3: P.V accumulation, lane owns 4 output dims.
__global__ void __launch_bounds__(128, 8) na3d_fwd(
    const float* __restrict__ Q,
    const float* __restrict__ K,
    const float* __restrict__ V,
    float* __restrict__ O)
{
    const int g    = blockIdx.x;   // 0..1023 query groups
    const int head = blockIdx.y;   // 0..7
    const int w0 = (g & 3) << 3;          // {0,8,16,24}
    const int h0 = ((g >> 2) & 15) << 1;  // {0,2,...,30}
    const int t  = g >> 6;                // 0..15

    const int warp = threadIdx.x >> 5;
    const int lane = threadIdx.x & 31;

    __shared__ float sc[4][NKEYS + 1];

    const float scale = 0.08838834764831845f;  // 128^-0.5
    const int st = min(max(t - 1, 0), Tz - KT);

    for (int i = 0; i < 4; ++i) {
        const int lidx = (warp << 2) + i;          // 0..15 within group
        const int hq = h0 + (lidx >> 3);
        const int wq = w0 + (lidx & 7);
        const int sh = min(max(hq - 3, 0), Hz - KH);
        const int sw = min(max(wq - 3, 0), Wz - KW);

        const size_t qoff =
            ((((size_t)t * Hz + hq) * Wz + wq) * NH + head) * DD + (lane << 2);
        float4 q4 = *(const float4*)(Q + qoff);
        q4.x *= scale; q4.y *= scale; q4.z *= scale; q4.w *= scale;

        // ---- pass 1: scores + running max ----
        float m = -1e30f;
        int cnt = 0;
        for (int dt = 0; dt < KT; ++dt) {
            for (int dh = 0; dh < KH; ++dh) {
                const float* kp = K +
                    ((((size_t)(st + dt) * Hz + (sh + dh)) * Wz + sw) * NH + head) * DD
                    + (lane << 2);
                #pragma unroll
                for (int dw = 0; dw < KW; ++dw) {
                    float4 k4 = *(const float4*)(kp + dw * (NH * DD));
                    float s = (q4.x * k4.x + q4.y * k4.y)
                            + (q4.z * k4.z + q4.w * k4.w);
                    #pragma unroll
                    for (int off = 16; off > 0; off >>= 1)
                        s += __shfl_xor_sync(0xffffffffu, s, off);
                    if (lane == 0) sc[warp][cnt + dw] = s;
                    m = fmaxf(m, s);
                }
                cnt += KW;
            }
        }
        __syncwarp();

        // ---- pass 2: softmax normalize factors ----
        float lsum = 0.f;
        #pragma unroll
        for (int j = lane; j < NKEYS; j += 32) {
            float p = __expf(sc[warp][j] - m);
            sc[warp][j] = p;
            lsum += p;
        }
        #pragma unroll
        for (int off = 16; off > 0; off >>= 1)
            lsum += __shfl_xor_sync(0xffffffffu, lsum, off);
        const float inv = 1.0f / lsum;
        __syncwarp();

        // ---- pass 3: P . V ----
        float4 acc = make_float4(0.f, 0.f, 0.f, 0.f);
        cnt = 0;
        for (int dt = 0; dt < KT; ++dt) {
            for (int dh = 0; dh < KH; ++dh) {
                const float* vp = V +
                    ((((size_t)(st + dt) * Hz + (sh + dh)) * Wz + sw) * NH + head) * DD
                    + (lane << 2);
                #pragma unroll
                for (int dw = 0; dw < KW; ++dw) {
                    float p = sc[warp][cnt + dw];
                    float4 v4 = *(const float4*)(vp + dw * (NH * DD));
                    acc.x += p * v4.x; acc.y += p * v4.y;
                    acc.z += p * v4.z; acc.w += p * v4.w;
                }
                cnt += KW;
            }
        }
        acc.x *= inv; acc.y *= inv; acc.z *= inv; acc.w *= inv;
        *(float4*)(O + qoff) = acc;
        __syncwarp();
    }
}

extern "C" void kernel_launch(void* const* d_in, const int* in_sizes, int n_in,
                              void* d_out, int out_size) {
    const float* q = (const float*)d_in[0];
    const float* k = (const float*)d_in[1];
    const float* v = (const float*)d_in[2];
    // d_in[3..5] are the scalar video_t/h/w (fixed 16/32/32; hardcoded above).
    (void)in_sizes; (void)n_in; (void)out_size;
    dim3 grid(1024, 8);   // 1024 query groups of 16, 8 heads
    na3d_fwd<<<grid, 128>>>(q, k, v, (float*)d_out);
}